// round 14
// baseline (speedup 1.0000x reference)
#include <cuda_runtime.h>
#include <cuda_fp16.h>
#include <cstdint>
#include <cstddef>

// ---------------- problem constants ----------------
#define T_   256
#define B_   64
#define I_   512
#define H_   1024
#define O_   512
#define K_   8
#define G3   3072
#define BH   65536
#define TBO  8388608

// ---------------- recurrence config (R10 skeleton, proven) ----------------
#define NCTA 128        // persistent CTAs; each owns 8 h-cols x 3 gates (N=24)
#define SMO_BRES 0          // resident Wh fp16 B-image: 49152
#define SMO_ABUF 49152      // 3 x 16384 A chunk ring (fp16)
#define SMO_GH   49152      // GH alias on A ring (4x64x24 fp32 = 24576), post-loop only
#define SMO_GXS  98304      // gx slice stage: 6144
#define SMO_HIST 104448     // h history ring 8x64x8 fp32 = 16384
#define SMO_MB   120832     // full[3]@0, cons[3]@24, gx@48, bres@56
#define SMEM_REQ 120960

// ---------------- device scratch ----------------
__device__ float    g_GX2[(size_t)T_*NCTA*B_*24];  // gate preact, slice-major
__device__ float    g_Hbuf[(size_t)(K_+T_)*BH];    // hidden ring fp32
__device__ float    g_w[K_*H_];                    // GL weights, idx0 oldest
__device__ __half   g_AImg16[2][BH];               // h A-fragment fp16, ping-pong (128KB ea)
__device__ __half   g_BImg16[(size_t)NCTA*24576];  // Wh B-fragment-major fp16 (6MB)
__device__ __half   g_WxImg16[(size_t)I_*G3];      // Wx fragment-major fp16 (3MB)
__device__ float    g_WoImg[(size_t)H_*O_];        // Wo fragment-major tf32 (2MB)
__device__ unsigned g_barG[8*32];                  // group counters, 128B apart
__device__ unsigned g_barR;                        // root counter

// ---------------- helpers ----------------
__device__ __forceinline__ uint32_t smem_u32(const void* p) {
    uint32_t a; asm("{ .reg .u64 t; cvta.to.shared.u64 t, %1; cvt.u32.u64 %0, t; }" : "=r"(a) : "l"(p));
    return a;
}
__device__ __forceinline__ void mbar_init(uint32_t m, uint32_t c) {
    asm volatile("mbarrier.init.shared.b64 [%0], %1;" :: "r"(m), "r"(c) : "memory");
}
__device__ __forceinline__ void mbar_arrive(uint32_t m) {
    asm volatile("mbarrier.arrive.shared.b64 _, [%0];" :: "r"(m) : "memory");
}
__device__ __forceinline__ void mbar_expect_tx(uint32_t m, uint32_t bytes) {
    asm volatile("mbarrier.arrive.expect_tx.shared.b64 _, [%0], %1;" :: "r"(m), "r"(bytes) : "memory");
}
__device__ __forceinline__ void mbar_wait(uint32_t m, uint32_t parity) {
    asm volatile(
        "{\n\t.reg .pred P;\n\t"
        "WL_%=:\n\t"
        "mbarrier.try_wait.parity.acquire.cta.shared::cta.b64 P, [%0], %1, 0x989680;\n\t"
        "@P bra WD_%=;\n\t"
        "bra WL_%=;\n\t"
        "WD_%=:\n\t}"
        :: "r"(m), "r"(parity) : "memory");
}
__device__ __forceinline__ void bulk_g2s(uint32_t dst, const void* src, uint32_t bytes, uint32_t mbar) {
    asm volatile("cp.async.bulk.shared::cluster.global.mbarrier::complete_tx::bytes [%0], [%1], %2, [%3];"
                 :: "r"(dst), "l"(src), "r"(bytes), "r"(mbar) : "memory");
}
__device__ __forceinline__ void cp16(uint32_t dst, const void* src) {
    asm volatile("cp.async.cg.shared.global [%0], [%1], 16;" :: "r"(dst), "l"(src));
}
__device__ __forceinline__ void cp_commit() { asm volatile("cp.async.commit_group;" ::: "memory"); }
__device__ __forceinline__ void cp_wait0() { asm volatile("cp.async.wait_group 0;" ::: "memory"); }
__device__ __forceinline__ void cp_wait1() { asm volatile("cp.async.wait_group 1;" ::: "memory"); }
__device__ __forceinline__ void mma_tf32(float* d, const uint32_t* a, const uint32_t* b) {
    asm("mma.sync.aligned.m16n8k8.row.col.f32.tf32.tf32.f32 "
        "{%0,%1,%2,%3},{%4,%5,%6,%7},{%8,%9},{%0,%1,%2,%3};"
        : "+f"(d[0]), "+f"(d[1]), "+f"(d[2]), "+f"(d[3])
        : "r"(a[0]), "r"(a[1]), "r"(a[2]), "r"(a[3]), "r"(b[0]), "r"(b[1]));
}
__device__ __forceinline__ void mma_fp16(float* d, const uint32_t* a, const uint32_t* b) {
    asm("mma.sync.aligned.m16n8k16.row.col.f32.f16.f16.f32 "
        "{%0,%1,%2,%3},{%4,%5,%6,%7},{%8,%9},{%0,%1,%2,%3};"
        : "+f"(d[0]), "+f"(d[1]), "+f"(d[2]), "+f"(d[3])
        : "r"(a[0]), "r"(a[1]), "r"(a[2]), "r"(a[3]), "r"(b[0]), "r"(b[1]));
}
__device__ __forceinline__ float to_tf32(float x) {
    float y; asm("cvt.rna.tf32.f32 %0, %1;" : "=f"(y) : "f"(x)); return y;
}
__device__ __forceinline__ uint32_t h2pack(float a, float b) {
    uint32_t r; asm("cvt.rn.f16x2.f32 %0, %1, %2;" : "=r"(r) : "f"(b), "f"(a));
    return r;
}
__device__ __forceinline__ float sigf(float x) { return 1.0f/(1.0f + __expf(-x)); }
__device__ __forceinline__ float tanhf_fast(float x) {
    float e = __expf(2.0f*x); return (e - 1.0f)/(e + 1.0f);
}

// fp16 A-fragment half-index for h[b][k]  (m16n8k16 .row A layout)
__device__ __forceinline__ int aimg16_idx(int b, int k) {
    int ks16 = k >> 4, k16 = k & 15;
    int mt = b >> 4, r16 = b & 15;
    int g = r16 & 7, hi = r16 >> 3;
    int half = k16 >> 3, tq = (k16 & 7) >> 1, lo = k16 & 1;
    int lane = g*4 + tq;
    int r = hi + 2*half;
    return (((ks16*4 + mt)*32 + lane)*4 + r)*2 + lo;
}

// ---------------- init ----------------
__global__ void init_kernel(const float* __restrict__ hid, const float* __restrict__ mp)
{
    int idx = blockIdx.x*blockDim.x + threadIdx.x;
    int stride = gridDim.x*blockDim.x;
    if (idx == 0) g_barR = 0u;
    if (idx < 8*32) g_barG[idx] = 0u;
    if (idx < H_) {
        float a = 0.5f / (1.0f + expf(-mp[idx]));
        float c = 1.0f;
        #pragma unroll
        for (int i = 0; i < K_; i++) {
            c *= ((float)i + a) / ((float)i + 1.0f);
            g_w[(K_-1-i)*H_ + idx] = c;
        }
    }
    for (int i = idx; i < K_*BH; i += stride) g_Hbuf[i] = hid[i];
    const float* h0 = hid + (size_t)(K_-1)*BH;
    for (int i = idx; i < BH; i += stride) {
        int b = i >> 10, k = i & 1023;
        g_AImg16[0][aimg16_idx(b, k)] = __float2half(h0[(size_t)b*H_ + k]);
    }
}

// ---------------- prep: Wh -> fp16 B-fragment image (slice = 8 h-cols, m16n8k16 .col B) ----------------
__global__ void prep_wht(const float* __restrict__ Wh)
{
    int idx = blockIdx.x*blockDim.x + threadIdx.x;
    int stride = gridDim.x*blockDim.x;
    const int total = H_*G3;
    for (int i = idx; i < total; i += stride) {
        int k = i / G3, col = i - k*G3;
        int gate = col >> 10, cw = col & 1023;
        int s = cw >> 3, hl8 = cw & 7;
        int nl = hl8*3 + gate;
        int nt = nl >> 3, g = nl & 7;
        int ks16 = k >> 4, k16 = k & 15;
        int r = k16 >> 3, tq = (k16 & 7) >> 1, lo = k16 & 1;
        int lane = g*4 + tq;
        size_t dst = ((((size_t)s*64 + ks16)*3 + nt)*32 + lane)*4 + r*2 + lo;
        g_BImg16[dst] = __float2half(Wh[i]);
    }
}

// ---------------- prep: weight -> tf32 GEMM B-fragment image (m16n8k8) ----------------
__global__ void prep_wimg(const float* __restrict__ W, float* __restrict__ img, int N, int K)
{
    int idx = blockIdx.x*blockDim.x + threadIdx.x;
    int stride = gridDim.x*blockDim.x;
    const int total = K*N, KC = K >> 4;
    for (int i = idx; i < total; i += stride) {
        int k = i / N, n = i - k*N;
        int nb = n >> 7, ntl = (n >> 3) & 15, g = n & 7;
        int kc = k >> 4, ks = (k >> 3) & 1, tq = k & 3, j = (k >> 2) & 1;
        int lane = g*4 + tq;
        size_t dst = ((((size_t)nb*KC + kc)*2 + ks)*16 + ntl)*32*2 + lane*2 + j;
        img[dst] = to_tf32(W[i]);
    }
}

// ---------------- prep: weight -> fp16 GEMM B-fragment image (m16n8k16 .col B) ----------------
__global__ void prep_wimg16(const float* __restrict__ W, __half* __restrict__ img, int N, int K)
{
    int idx = blockIdx.x*blockDim.x + threadIdx.x;
    int stride = gridDim.x*blockDim.x;
    const int total = K*N, KC = K >> 4;
    for (int i = idx; i < total; i += stride) {
        int k = i / N, n = i - k*N;
        int nb = n >> 7, ntl = (n >> 3) & 15, g = n & 7;
        int ks16 = k >> 4, k16 = k & 15;
        int r = k16 >> 3, tq = (k16 & 7) >> 1, lo = k16 & 1;
        int lane = g*4 + tq;
        size_t dst = ((((size_t)nb*KC + ks16)*16 + ntl)*32 + lane)*4 + r*2 + lo;
        img[dst] = __float2half(W[i]);
    }
}

// ---------------- tf32 HMMA GEMM: C = A @ W + bias (out GEMM) ----------------
__global__ __launch_bounds__(256) void mma_gemm(
    const float* __restrict__ A, const float* __restrict__ Wimg,
    const float* __restrict__ bias, float* __restrict__ C,
    int M, int N, int K, int mode)
{
    __shared__ float As[2][128][20];
    __shared__ float Bs[2][2048];
    const int tid = threadIdx.x;
    const int w = tid >> 5, l = tid & 31;
    const int wm = w >> 1, wn = w & 1;
    const int bn = blockIdx.x, bm = blockIdx.y;
    const int KC = K >> 4;
    const int g = l >> 2, tq = l & 3;

    float acc[2][8][4];
    #pragma unroll
    for (int mi = 0; mi < 2; mi++)
        #pragma unroll
        for (int ni = 0; ni < 8; ni++)
            #pragma unroll
            for (int q = 0; q < 4; q++) acc[mi][ni][q] = 0.0f;

    const float* Bsrc = Wimg + (size_t)bn*KC*2048;
    const int arow = tid >> 2, aseg = tid & 3;

    {
        #pragma unroll
        for (int r = 0; r < 2; r++) {
            int row = arow + r*64;
            cp16(smem_u32(&As[0][row][aseg*4]), A + (size_t)(bm*128 + row)*K + aseg*4);
            cp16(smem_u32(&Bs[0][(tid + r*256)*4]), Bsrc + (size_t)(tid + r*256)*4);
        }
        cp_commit();
    }

    int buf = 0;
    for (int kc = 0; kc < KC; kc++) {
        if (kc + 1 < KC) {
            #pragma unroll
            for (int r = 0; r < 2; r++) {
                int row = arow + r*64;
                cp16(smem_u32(&As[buf^1][row][aseg*4]),
                     A + (size_t)(bm*128 + row)*K + (kc+1)*16 + aseg*4);
                cp16(smem_u32(&Bs[buf^1][(tid + r*256)*4]),
                     Bsrc + (size_t)(kc+1)*2048 + (tid + r*256)*4);
            }
            cp_commit();
            cp_wait1();
        } else {
            cp_wait0();
        }
        __syncthreads();

        #pragma unroll
        for (int ks = 0; ks < 2; ks++) {
            uint32_t afr[2][4];
            #pragma unroll
            for (int mi = 0; mi < 2; mi++) {
                int r0 = wm*32 + mi*16 + g;
                afr[mi][0] = __float_as_uint(to_tf32(As[buf][r0    ][ks*8 + tq    ]));
                afr[mi][1] = __float_as_uint(to_tf32(As[buf][r0 + 8][ks*8 + tq    ]));
                afr[mi][2] = __float_as_uint(to_tf32(As[buf][r0    ][ks*8 + tq + 4]));
                afr[mi][3] = __float_as_uint(to_tf32(As[buf][r0 + 8][ks*8 + tq + 4]));
            }
            #pragma unroll
            for (int ni = 0; ni < 8; ni++) {
                float2 bv = *(const float2*)&Bs[buf][((ks*16 + wn*8 + ni)*32 + l)*2];
                uint32_t bfr[2] = { __float_as_uint(bv.x), __float_as_uint(bv.y) };
                #pragma unroll
                for (int mi = 0; mi < 2; mi++)
                    mma_tf32(acc[mi][ni], afr[mi], bfr);
            }
        }
        __syncthreads();
        buf ^= 1;
    }

    #pragma unroll
    for (int mi = 0; mi < 2; mi++) {
        int row0 = bm*128 + wm*32 + mi*16 + g;
        #pragma unroll
        for (int ni = 0; ni < 8; ni++) {
            int col = bn*128 + wn*64 + ni*8 + tq*2;
            float b0 = bias[col], b1 = bias[col+1];
            if (mode == 0) {
                *(float2*)&C[(size_t)row0*N + col] =
                    make_float2(acc[mi][ni][0] + b0, acc[mi][ni][1] + b1);
                *(float2*)&C[(size_t)(row0 + 8)*N + col] =
                    make_float2(acc[mi][ni][2] + b0, acc[mi][ni][3] + b1);
            } else {
                int gate = col >> 10, cw = col & 1023;
                int s2 = cw >> 3, hl = cw & 7;
                int tt = row0 >> 6, bb = row0 & 63;
                size_t base = ((size_t)tt*NCTA + s2)*64;
                *(float2*)&C[(base + bb)*24 + gate*8 + hl] =
                    make_float2(acc[mi][ni][0] + b0, acc[mi][ni][1] + b1);
                *(float2*)&C[(base + bb + 8)*24 + gate*8 + hl] =
                    make_float2(acc[mi][ni][2] + b0, acc[mi][ni][3] + b1);
            }
        }
    }
}

// ---------------- fp16 HMMA GEMM: C = A @ W + bias (gx path, validated R13) ----------------
__global__ __launch_bounds__(256) void mma_gemm16(
    const float* __restrict__ A, const __half* __restrict__ Wimg,
    const float* __restrict__ bias, float* __restrict__ C,
    int M, int N, int K, int mode)
{
    __shared__ float As[2][128][20];
    __shared__ __half Bs[2][2048];
    const int tid = threadIdx.x;
    const int w = tid >> 5, l = tid & 31;
    const int wm = w >> 1, wn = w & 1;
    const int bn = blockIdx.x, bm = blockIdx.y;
    const int KC = K >> 4;
    const int g = l >> 2, tq = l & 3;

    float acc[2][8][4];
    #pragma unroll
    for (int mi = 0; mi < 2; mi++)
        #pragma unroll
        for (int ni = 0; ni < 8; ni++)
            #pragma unroll
            for (int q = 0; q < 4; q++) acc[mi][ni][q] = 0.0f;

    const __half* Bsrc = Wimg + (size_t)bn*KC*2048;
    const int arow = tid >> 2, aseg = tid & 3;

    {
        #pragma unroll
        for (int r = 0; r < 2; r++) {
            int row = arow + r*64;
            cp16(smem_u32(&As[0][row][aseg*4]), A + (size_t)(bm*128 + row)*K + aseg*4);
        }
        cp16(smem_u32(&Bs[0][tid*8]), Bsrc + (size_t)tid*8);
        cp_commit();
    }

    int buf = 0;
    for (int kc = 0; kc < KC; kc++) {
        if (kc + 1 < KC) {
            #pragma unroll
            for (int r = 0; r < 2; r++) {
                int row = arow + r*64;
                cp16(smem_u32(&As[buf^1][row][aseg*4]),
                     A + (size_t)(bm*128 + row)*K + (kc+1)*16 + aseg*4);
            }
            cp16(smem_u32(&Bs[buf^1][tid*8]), Bsrc + (size_t)(kc+1)*2048 + tid*8);
            cp_commit();
            cp_wait1();
        } else {
            cp_wait0();
        }
        __syncthreads();

        uint32_t afr[2][4];
        #pragma unroll
        for (int mi = 0; mi < 2; mi++) {
            int r0 = wm*32 + mi*16 + g;
            float2 v0 = *(const float2*)&As[buf][r0    ][tq*2];
            float2 v1 = *(const float2*)&As[buf][r0 + 8][tq*2];
            float2 v2 = *(const float2*)&As[buf][r0    ][8 + tq*2];
            float2 v3 = *(const float2*)&As[buf][r0 + 8][8 + tq*2];
            afr[mi][0] = h2pack(v0.x, v0.y);
            afr[mi][1] = h2pack(v1.x, v1.y);
            afr[mi][2] = h2pack(v2.x, v2.y);
            afr[mi][3] = h2pack(v3.x, v3.y);
        }
        #pragma unroll
        for (int ni = 0; ni < 8; ni++) {
            uint2 bv = *(const uint2*)&Bs[buf][((wn*8 + ni)*32 + l)*4];
            uint32_t bfr[2] = { bv.x, bv.y };
            #pragma unroll
            for (int mi = 0; mi < 2; mi++)
                mma_fp16(acc[mi][ni], afr[mi], bfr);
        }
        __syncthreads();
        buf ^= 1;
    }

    #pragma unroll
    for (int mi = 0; mi < 2; mi++) {
        int row0 = bm*128 + wm*32 + mi*16 + g;
        #pragma unroll
        for (int ni = 0; ni < 8; ni++) {
            int col = bn*128 + wn*64 + ni*8 + tq*2;
            float b0 = bias[col], b1 = bias[col+1];
            if (mode == 0) {
                *(float2*)&C[(size_t)row0*N + col] =
                    make_float2(acc[mi][ni][0] + b0, acc[mi][ni][1] + b1);
                *(float2*)&C[(size_t)(row0 + 8)*N + col] =
                    make_float2(acc[mi][ni][2] + b0, acc[mi][ni][3] + b1);
            } else {
                int gate = col >> 10, cw = col & 1023;
                int s2 = cw >> 3, hl = cw & 7;
                int tt = row0 >> 6, bb = row0 & 63;
                size_t base = ((size_t)tt*NCTA + s2)*64;
                *(float2*)&C[(base + bb)*24 + gate*8 + hl] =
                    make_float2(acc[mi][ni][0] + b0, acc[mi][ni][1] + b1);
                *(float2*)&C[(base + bb + 8)*24 + gate*8 + hl] =
                    make_float2(acc[mi][ni][2] + b0, acc[mi][ni][3] + b1);
            }
        }
    }
}

// ---------------- persistent fp16-HMMA recurrence (R10 + tree barrier) ----------------
extern __shared__ char smemRaw[];

__global__ __launch_bounds__(256, 1) void recur_mma()
{
    const int tid = threadIdx.x;
    const int w   = tid >> 5;
    const int l   = tid & 31;
    const int mw  = w & 1;           // M half: mt = 2*mw + mi
    const int ksp = w >> 1;          // K split 0..3
    const int s   = blockIdx.x;      // slice: h-cols s*8..s*8+7
    uint32_t smb  = smem_u32(smemRaw);
    uint32_t mbF0 = smb + SMO_MB;        // full[i] @ +8i
    uint32_t mbC0 = smb + SMO_MB + 24;   // cons[i] @ +8i
    uint32_t mbGX = smb + SMO_MB + 48;
    uint32_t mbBR = smb + SMO_MB + 56;
    const char* BresB = smemRaw + SMO_BRES;
    float* GH   = (float*)(smemRaw + SMO_GH);
    float* gxs  = (float*)(smemRaw + SMO_GXS);
    float* hist = (float*)(smemRaw + SMO_HIST);

    if (tid == 0) {
        #pragma unroll
        for (int i = 0; i < 3; i++) { mbar_init(mbF0 + 8*i, 1); mbar_init(mbC0 + 8*i, 8); }
        mbar_init(mbGX, 1); mbar_init(mbBR, 1);
    }
    __syncthreads();
    if (tid == 0) {
        mbar_expect_tx(mbBR, 49152);
        bulk_g2s(smb + SMO_BRES, (const char*)g_BImg16 + (size_t)s*49152, 49152, mbBR);
    }

    // hist ring init: hist[k][b][h8]
    for (int i = tid; i < K_*B_*8; i += 256) {
        int k = i >> 9, b = (i >> 3) & 63, h2 = i & 7;
        hist[i] = g_Hbuf[(size_t)k*BH + (size_t)b*H_ + s*8 + h2];
    }

    // epilogue constants
    const int hl8  = tid & 7;
    const int brow = tid >> 3;       // 0..31; b = brow, brow+32
    const int hc   = s*8 + hl8;
    float wk[K_];
    #pragma unroll
    for (int kk = 0; kk < K_; kk++) wk[kk] = g_w[kk*H_ + hc];
    // fp16 A-image write constants for k = hc
    const int a_ks16 = s >> 1;
    const int a_half = s & 1;
    const int a_tq   = hl8 >> 1;
    const int a_lo   = hl8 & 1;
    const int gg = l >> 2, tq = l & 3;
    const int grp = s >> 4;          // barrier group 0..7

    mbar_wait(mbBR, 0);
    __syncthreads();

    for (int t = 0; t < T_; t++) {
        const char* aimg = (const char*)g_AImg16[t & 1];
        if (tid == 0) {
            mbar_expect_tx(mbGX, 6144);
            bulk_g2s(smb + SMO_GXS,
                     g_GX2 + (((size_t)t*NCTA + s)*64)*24, 6144, mbGX);
            #pragma unroll
            for (int cp = 0; cp < 3; cp++) {
                int gc = t*8 + cp, buf = gc % 3, f = gc / 3;
                if (f > 0) mbar_wait(mbC0 + 8*buf, (f - 1) & 1);
                mbar_expect_tx(mbF0 + 8*buf, 16384);
                bulk_g2s(smb + SMO_ABUF + buf*16384, aimg + (size_t)cp*16384, 16384, mbF0 + 8*buf);
            }
        }

        float acc[2][3][4];
        #pragma unroll
        for (int mi = 0; mi < 2; mi++)
            #pragma unroll
            for (int ni = 0; ni < 3; ni++)
                #pragma unroll
                for (int q = 0; q < 4; q++) acc[mi][ni][q] = 0.0f;

        #pragma unroll 1
        for (int c = 0; c < 8; c++) {
            const int gc = t*8 + c, buf = gc % 3, f = gc / 3;
            mbar_wait(mbF0 + 8*buf, f & 1);
            const char* Ab = smemRaw + SMO_ABUF + buf*16384;
            #pragma unroll
            for (int kl = 0; kl < 2; kl++) {
                const int ksl = ksp*2 + kl;          // local ks16 in chunk (0..7)
                const int ksg = c*8 + ksl;           // global ks16 (0..63)
                uint32_t afr[2][4];
                *(uint4*)afr[0] = *(const uint4*)(Ab + ((size_t)((ksl*4 + 2*mw    )*32 + l))*16);
                *(uint4*)afr[1] = *(const uint4*)(Ab + ((size_t)((ksl*4 + 2*mw + 1)*32 + l))*16);
                #pragma unroll
                for (int ni = 0; ni < 3; ni++) {
                    uint2 bv = *(const uint2*)(BresB + ((size_t)((ksg*3 + ni)*32 + l))*8);
                    uint32_t bfr[2] = { bv.x, bv.y };
                    #pragma unroll
                    for (int mi = 0; mi < 2; mi++)
                        mma_fp16(acc[mi][ni], afr[mi], bfr);
                }
            }
            __syncwarp();
            if (l == 0) mbar_arrive(mbC0 + 8*buf);
            if (tid == 0 && c < 5) {
                int gc2 = gc + 3, buf2 = gc2 % 3, f2 = gc2 / 3;
                mbar_wait(mbC0 + 8*buf2, (f2 - 1) & 1);
                mbar_expect_tx(mbF0 + 8*buf2, 16384);
                bulk_g2s(smb + SMO_ABUF + buf2*16384, aimg + (size_t)(c + 3)*16384, 16384, mbF0 + 8*buf2);
            }
        }
        __syncthreads();   // all buffer reads done -> GH alias safe

        // dump C fragments: GH[ksp][b][24]
        #pragma unroll
        for (int mi = 0; mi < 2; mi++) {
            int row0 = (2*mw + mi)*16 + gg;
            #pragma unroll
            for (int ni = 0; ni < 3; ni++) {
                int colb = ni*8 + tq*2;
                *(float2*)&GH[ksp*1536 + row0*24 + colb]       = make_float2(acc[mi][ni][0], acc[mi][ni][1]);
                *(float2*)&GH[ksp*1536 + (row0 + 8)*24 + colb] = make_float2(acc[mi][ni][2], acc[mi][ni][3]);
            }
        }
        __syncthreads();
        mbar_wait(mbGX, (uint32_t)(t & 1));

        // gates + fractional memory (2 (b,hl8) pairs per thread)
        __half* imgn = g_AImg16[(t + 1) & 1];
        #pragma unroll
        for (int i = 0; i < 2; i++) {
            int b = brow + i*32;
            int gi = b*24 + hl8*3;
            float gz = GH[gi] + GH[1536 + gi] + GH[3072 + gi] + GH[4608 + gi];
            float gr = GH[gi+1] + GH[1536 + gi+1] + GH[3072 + gi+1] + GH[4608 + gi+1];
            float gn = GH[gi+2] + GH[1536 + gi+2] + GH[3072 + gi+2] + GH[4608 + gi+2];
            float z = sigf(gxs[b*24 + hl8]          + gz);
            float r = sigf(gxs[b*24 + 8 + hl8]      + gr);
            float n = tanhf_fast(gxs[b*24 + 16 + hl8] + r*gn);
            float mem = 0.f;
            #pragma unroll
            for (int kk = 0; kk < K_; kk++)
                mem = fmaf(wk[kk], hist[((t + kk) & 7)*512 + b*8 + hl8], mem);
            float hn = (1.0f - z)*n + z*mem;
            hist[(t & 7)*512 + b*8 + hl8] = hn;
            g_Hbuf[(size_t)(K_ + t)*BH + (size_t)b*H_ + hc] = hn;
            // fp16 A-image write for next step
            int mt = b >> 4, r16 = b & 15;
            int g2 = r16 & 7, hi = r16 >> 3;
            int lane2 = g2*4 + a_tq;
            int rreg = hi + 2*a_half;
            imgn[(((a_ks16*4 + mt)*32 + lane2)*4 + rreg)*2 + a_lo] = __float2half(hn);
        }

        // ---- two-level tree barrier ----
        __threadfence();
        __syncthreads();
        if (tid == 0) {
            unsigned old = atomicAdd(&g_barG[grp*32], 1u);
            if (old == 16u*(unsigned)(t + 1) - 1u)
                atomicAdd(&g_barR, 1u);
            unsigned target = 8u*(unsigned)(t + 1);
            while (*(volatile unsigned*)&g_barR < target) { __nanosleep(32); }
        }
        __syncthreads();
    }
}

// ---------------- tail ----------------
__global__ void tail_kernel(float* __restrict__ outTail)
{
    const int n = K_*BH;
    for (int i = blockIdx.x*blockDim.x + threadIdx.x; i < n; i += gridDim.x*blockDim.x)
        outTail[i] = g_Hbuf[(size_t)T_*BH + i];
}

// ---------------- launch ----------------
extern "C" void kernel_launch(void* const* d_in, const int* in_sizes, int n_in,
                              void* d_out, int out_size)
{
    const float* inputs = (const float*)d_in[0];
    const float* hidden = (const float*)d_in[1];
    const float* Wx     = (const float*)d_in[2];
    const float* Wh     = (const float*)d_in[3];
    const float* b      = (const float*)d_in[4];
    const float* Wo     = (const float*)d_in[5];
    const float* bo     = (const float*)d_in[6];
    const float* mp     = (const float*)d_in[7];
    float* out = (float*)d_out;

    void* gxp = nullptr; cudaGetSymbolAddress(&gxp, g_GX2);
    void* hbp = nullptr; cudaGetSymbolAddress(&hbp, g_Hbuf);
    void* wxi = nullptr; cudaGetSymbolAddress(&wxi, g_WxImg16);
    void* woi = nullptr; cudaGetSymbolAddress(&woi, g_WoImg);

    cudaFuncSetAttribute(recur_mma, cudaFuncAttributeMaxDynamicSharedMemorySize, SMEM_REQ);

    init_kernel<<<256, 256>>>(hidden, mp);
    prep_wht<<<512, 256>>>(Wh);
    prep_wimg16<<<512, 256>>>(Wx, (__half*)wxi, G3, I_);
    prep_wimg<<<512, 256>>>(Wo, (float*)woi, O_, H_);

    // GX2 = X @ Wx + b  (fp16 operands, fp32 accum, slice-major output)
    mma_gemm16<<<dim3(G3/128, (T_*B_)/128), 256>>>(inputs, (const __half*)wxi, b,
                                                   (float*)gxp, T_*B_, G3, I_, 1);
    // recurrence
    recur_mma<<<NCTA, 256, SMEM_REQ>>>();
    // outs = H_all @ Wo + bo  (tf32, clean output path)
    mma_gemm<<<dim3(O_/128, (T_*B_)/128), 256>>>((const float*)hbp + (size_t)K_*BH,
                                                 (const float*)woi, bo, out,
                                                 T_*B_, O_, H_, 0);
    if (out_size >= TBO + K_*BH)
        tail_kernel<<<256, 256>>>(out + TBO);
}

// round 15
// speedup vs baseline: 1.2189x; 1.2189x over previous
#include <cuda_runtime.h>
#include <cuda_fp16.h>
#include <cstdint>
#include <cstddef>

// ---------------- problem constants ----------------
#define T_   256
#define B_   64
#define I_   512
#define H_   1024
#define O_   512
#define K_   8
#define G3   3072
#define BH   65536
#define TBO  8388608

// ---------------- recurrence config (v10: 8-deep A staging) ----------------
#define NCTA 128        // persistent CTAs; each owns 8 h-cols x 3 gates (N=24)
#define SMO_BRES 0          // resident Wh fp16 B-image: 49152
#define SMO_ABUF 49152      // 8 x 16384 A chunk buffers (1:1 with chunks) = 131072
#define SMO_GH   49152      // GH alias on A buffers (4x64x24 fp32 = 24576), post-loop only
#define SMO_GXS  180224     // gx slice stage: 6144
#define SMO_HIST 186368     // h history ring 8x64x8 fp32 = 16384
#define SMO_MB   202752     // full[8]@0..63, gx@64, bres@72
#define SMEM_REQ 202880

// ---------------- device scratch ----------------
__device__ float    g_GX2[(size_t)T_*NCTA*B_*24];  // gate preact, slice-major
__device__ float    g_Hbuf[(size_t)(K_+T_)*BH];    // hidden ring fp32
__device__ float    g_w[K_*H_];                    // GL weights, idx0 oldest
__device__ __half   g_AImg16[2][BH];               // h A-fragment fp16, ping-pong (128KB ea)
__device__ __half   g_BImg16[(size_t)NCTA*24576];  // Wh B-fragment-major fp16 (6MB)
__device__ __half   g_WxImg16[(size_t)I_*G3];      // Wx fragment-major fp16 (3MB)
__device__ float    g_WoImg[(size_t)H_*O_];        // Wo fragment-major tf32 (2MB)
__device__ unsigned g_bar;

// ---------------- helpers ----------------
__device__ __forceinline__ uint32_t smem_u32(const void* p) {
    uint32_t a; asm("{ .reg .u64 t; cvta.to.shared.u64 t, %1; cvt.u32.u64 %0, t; }" : "=r"(a) : "l"(p));
    return a;
}
__device__ __forceinline__ void mbar_init(uint32_t m, uint32_t c) {
    asm volatile("mbarrier.init.shared.b64 [%0], %1;" :: "r"(m), "r"(c) : "memory");
}
__device__ __forceinline__ void mbar_expect_tx(uint32_t m, uint32_t bytes) {
    asm volatile("mbarrier.arrive.expect_tx.shared.b64 _, [%0], %1;" :: "r"(m), "r"(bytes) : "memory");
}
__device__ __forceinline__ void mbar_wait(uint32_t m, uint32_t parity) {
    asm volatile(
        "{\n\t.reg .pred P;\n\t"
        "WL_%=:\n\t"
        "mbarrier.try_wait.parity.acquire.cta.shared::cta.b64 P, [%0], %1, 0x989680;\n\t"
        "@P bra WD_%=;\n\t"
        "bra WL_%=;\n\t"
        "WD_%=:\n\t}"
        :: "r"(m), "r"(parity) : "memory");
}
__device__ __forceinline__ void bulk_g2s(uint32_t dst, const void* src, uint32_t bytes, uint32_t mbar) {
    asm volatile("cp.async.bulk.shared::cluster.global.mbarrier::complete_tx::bytes [%0], [%1], %2, [%3];"
                 :: "r"(dst), "l"(src), "r"(bytes), "r"(mbar) : "memory");
}
__device__ __forceinline__ void cp16(uint32_t dst, const void* src) {
    asm volatile("cp.async.cg.shared.global [%0], [%1], 16;" :: "r"(dst), "l"(src));
}
__device__ __forceinline__ void cp_commit() { asm volatile("cp.async.commit_group;" ::: "memory"); }
__device__ __forceinline__ void cp_wait0() { asm volatile("cp.async.wait_group 0;" ::: "memory"); }
__device__ __forceinline__ void cp_wait1() { asm volatile("cp.async.wait_group 1;" ::: "memory"); }
__device__ __forceinline__ void mma_tf32(float* d, const uint32_t* a, const uint32_t* b) {
    asm("mma.sync.aligned.m16n8k8.row.col.f32.tf32.tf32.f32 "
        "{%0,%1,%2,%3},{%4,%5,%6,%7},{%8,%9},{%0,%1,%2,%3};"
        : "+f"(d[0]), "+f"(d[1]), "+f"(d[2]), "+f"(d[3])
        : "r"(a[0]), "r"(a[1]), "r"(a[2]), "r"(a[3]), "r"(b[0]), "r"(b[1]));
}
__device__ __forceinline__ void mma_fp16(float* d, const uint32_t* a, const uint32_t* b) {
    asm("mma.sync.aligned.m16n8k16.row.col.f32.f16.f16.f32 "
        "{%0,%1,%2,%3},{%4,%5,%6,%7},{%8,%9},{%0,%1,%2,%3};"
        : "+f"(d[0]), "+f"(d[1]), "+f"(d[2]), "+f"(d[3])
        : "r"(a[0]), "r"(a[1]), "r"(a[2]), "r"(a[3]), "r"(b[0]), "r"(b[1]));
}
__device__ __forceinline__ float to_tf32(float x) {
    float y; asm("cvt.rna.tf32.f32 %0, %1;" : "=f"(y) : "f"(x)); return y;
}
__device__ __forceinline__ uint32_t h2pack(float a, float b) {
    uint32_t r; asm("cvt.rn.f16x2.f32 %0, %1, %2;" : "=r"(r) : "f"(b), "f"(a));
    return r;
}
__device__ __forceinline__ float sigf(float x) { return 1.0f/(1.0f + __expf(-x)); }
__device__ __forceinline__ float tanhf_fast(float x) {
    float e = __expf(2.0f*x); return (e - 1.0f)/(e + 1.0f);
}

// fp16 A-fragment half-index for h[b][k]  (m16n8k16 .row A layout)
__device__ __forceinline__ int aimg16_idx(int b, int k) {
    int ks16 = k >> 4, k16 = k & 15;
    int mt = b >> 4, r16 = b & 15;
    int g = r16 & 7, hi = r16 >> 3;
    int half = k16 >> 3, tq = (k16 & 7) >> 1, lo = k16 & 1;
    int lane = g*4 + tq;
    int r = hi + 2*half;
    return (((ks16*4 + mt)*32 + lane)*4 + r)*2 + lo;
}

// ---------------- init ----------------
__global__ void init_kernel(const float* __restrict__ hid, const float* __restrict__ mp)
{
    int idx = blockIdx.x*blockDim.x + threadIdx.x;
    int stride = gridDim.x*blockDim.x;
    if (idx == 0) g_bar = 0u;
    if (idx < H_) {
        float a = 0.5f / (1.0f + expf(-mp[idx]));
        float c = 1.0f;
        #pragma unroll
        for (int i = 0; i < K_; i++) {
            c *= ((float)i + a) / ((float)i + 1.0f);
            g_w[(K_-1-i)*H_ + idx] = c;
        }
    }
    for (int i = idx; i < K_*BH; i += stride) g_Hbuf[i] = hid[i];
    const float* h0 = hid + (size_t)(K_-1)*BH;
    for (int i = idx; i < BH; i += stride) {
        int b = i >> 10, k = i & 1023;
        g_AImg16[0][aimg16_idx(b, k)] = __float2half(h0[(size_t)b*H_ + k]);
    }
}

// ---------------- prep: Wh -> fp16 B-fragment image (slice = 8 h-cols, m16n8k16 .col B) ----------------
__global__ void prep_wht(const float* __restrict__ Wh)
{
    int idx = blockIdx.x*blockDim.x + threadIdx.x;
    int stride = gridDim.x*blockDim.x;
    const int total = H_*G3;
    for (int i = idx; i < total; i += stride) {
        int k = i / G3, col = i - k*G3;
        int gate = col >> 10, cw = col & 1023;
        int s = cw >> 3, hl8 = cw & 7;
        int nl = hl8*3 + gate;
        int nt = nl >> 3, g = nl & 7;
        int ks16 = k >> 4, k16 = k & 15;
        int r = k16 >> 3, tq = (k16 & 7) >> 1, lo = k16 & 1;
        int lane = g*4 + tq;
        size_t dst = ((((size_t)s*64 + ks16)*3 + nt)*32 + lane)*4 + r*2 + lo;
        g_BImg16[dst] = __float2half(Wh[i]);
    }
}

// ---------------- prep: weight -> tf32 GEMM B-fragment image (m16n8k8) ----------------
__global__ void prep_wimg(const float* __restrict__ W, float* __restrict__ img, int N, int K)
{
    int idx = blockIdx.x*blockDim.x + threadIdx.x;
    int stride = gridDim.x*blockDim.x;
    const int total = K*N, KC = K >> 4;
    for (int i = idx; i < total; i += stride) {
        int k = i / N, n = i - k*N;
        int nb = n >> 7, ntl = (n >> 3) & 15, g = n & 7;
        int kc = k >> 4, ks = (k >> 3) & 1, tq = k & 3, j = (k >> 2) & 1;
        int lane = g*4 + tq;
        size_t dst = ((((size_t)nb*KC + kc)*2 + ks)*16 + ntl)*32*2 + lane*2 + j;
        img[dst] = to_tf32(W[i]);
    }
}

// ---------------- prep: weight -> fp16 GEMM B-fragment image (m16n8k16 .col B) ----------------
__global__ void prep_wimg16(const float* __restrict__ W, __half* __restrict__ img, int N, int K)
{
    int idx = blockIdx.x*blockDim.x + threadIdx.x;
    int stride = gridDim.x*blockDim.x;
    const int total = K*N, KC = K >> 4;
    for (int i = idx; i < total; i += stride) {
        int k = i / N, n = i - k*N;
        int nb = n >> 7, ntl = (n >> 3) & 15, g = n & 7;
        int ks16 = k >> 4, k16 = k & 15;
        int r = k16 >> 3, tq = (k16 & 7) >> 1, lo = k16 & 1;
        int lane = g*4 + tq;
        size_t dst = ((((size_t)nb*KC + ks16)*16 + ntl)*32 + lane)*4 + r*2 + lo;
        img[dst] = __float2half(W[i]);
    }
}

// ---------------- tf32 HMMA GEMM: C = A @ W + bias (out GEMM) ----------------
__global__ __launch_bounds__(256) void mma_gemm(
    const float* __restrict__ A, const float* __restrict__ Wimg,
    const float* __restrict__ bias, float* __restrict__ C,
    int M, int N, int K, int mode)
{
    __shared__ float As[2][128][20];
    __shared__ float Bs[2][2048];
    const int tid = threadIdx.x;
    const int w = tid >> 5, l = tid & 31;
    const int wm = w >> 1, wn = w & 1;
    const int bn = blockIdx.x, bm = blockIdx.y;
    const int KC = K >> 4;
    const int g = l >> 2, tq = l & 3;

    float acc[2][8][4];
    #pragma unroll
    for (int mi = 0; mi < 2; mi++)
        #pragma unroll
        for (int ni = 0; ni < 8; ni++)
            #pragma unroll
            for (int q = 0; q < 4; q++) acc[mi][ni][q] = 0.0f;

    const float* Bsrc = Wimg + (size_t)bn*KC*2048;
    const int arow = tid >> 2, aseg = tid & 3;

    {
        #pragma unroll
        for (int r = 0; r < 2; r++) {
            int row = arow + r*64;
            cp16(smem_u32(&As[0][row][aseg*4]), A + (size_t)(bm*128 + row)*K + aseg*4);
            cp16(smem_u32(&Bs[0][(tid + r*256)*4]), Bsrc + (size_t)(tid + r*256)*4);
        }
        cp_commit();
    }

    int buf = 0;
    for (int kc = 0; kc < KC; kc++) {
        if (kc + 1 < KC) {
            #pragma unroll
            for (int r = 0; r < 2; r++) {
                int row = arow + r*64;
                cp16(smem_u32(&As[buf^1][row][aseg*4]),
                     A + (size_t)(bm*128 + row)*K + (kc+1)*16 + aseg*4);
                cp16(smem_u32(&Bs[buf^1][(tid + r*256)*4]),
                     Bsrc + (size_t)(kc+1)*2048 + (tid + r*256)*4);
            }
            cp_commit();
            cp_wait1();
        } else {
            cp_wait0();
        }
        __syncthreads();

        #pragma unroll
        for (int ks = 0; ks < 2; ks++) {
            uint32_t afr[2][4];
            #pragma unroll
            for (int mi = 0; mi < 2; mi++) {
                int r0 = wm*32 + mi*16 + g;
                afr[mi][0] = __float_as_uint(to_tf32(As[buf][r0    ][ks*8 + tq    ]));
                afr[mi][1] = __float_as_uint(to_tf32(As[buf][r0 + 8][ks*8 + tq    ]));
                afr[mi][2] = __float_as_uint(to_tf32(As[buf][r0    ][ks*8 + tq + 4]));
                afr[mi][3] = __float_as_uint(to_tf32(As[buf][r0 + 8][ks*8 + tq + 4]));
            }
            #pragma unroll
            for (int ni = 0; ni < 8; ni++) {
                float2 bv = *(const float2*)&Bs[buf][((ks*16 + wn*8 + ni)*32 + l)*2];
                uint32_t bfr[2] = { __float_as_uint(bv.x), __float_as_uint(bv.y) };
                #pragma unroll
                for (int mi = 0; mi < 2; mi++)
                    mma_tf32(acc[mi][ni], afr[mi], bfr);
            }
        }
        __syncthreads();
        buf ^= 1;
    }

    #pragma unroll
    for (int mi = 0; mi < 2; mi++) {
        int row0 = bm*128 + wm*32 + mi*16 + g;
        #pragma unroll
        for (int ni = 0; ni < 8; ni++) {
            int col = bn*128 + wn*64 + ni*8 + tq*2;
            float b0 = bias[col], b1 = bias[col+1];
            if (mode == 0) {
                *(float2*)&C[(size_t)row0*N + col] =
                    make_float2(acc[mi][ni][0] + b0, acc[mi][ni][1] + b1);
                *(float2*)&C[(size_t)(row0 + 8)*N + col] =
                    make_float2(acc[mi][ni][2] + b0, acc[mi][ni][3] + b1);
            } else {
                int gate = col >> 10, cw = col & 1023;
                int s2 = cw >> 3, hl = cw & 7;
                int tt = row0 >> 6, bb = row0 & 63;
                size_t base = ((size_t)tt*NCTA + s2)*64;
                *(float2*)&C[(base + bb)*24 + gate*8 + hl] =
                    make_float2(acc[mi][ni][0] + b0, acc[mi][ni][1] + b1);
                *(float2*)&C[(base + bb + 8)*24 + gate*8 + hl] =
                    make_float2(acc[mi][ni][2] + b0, acc[mi][ni][3] + b1);
            }
        }
    }
}

// ---------------- fp16 HMMA GEMM: C = A @ W + bias (gx path, validated R13) ----------------
__global__ __launch_bounds__(256) void mma_gemm16(
    const float* __restrict__ A, const __half* __restrict__ Wimg,
    const float* __restrict__ bias, float* __restrict__ C,
    int M, int N, int K, int mode)
{
    __shared__ float As[2][128][20];
    __shared__ __half Bs[2][2048];
    const int tid = threadIdx.x;
    const int w = tid >> 5, l = tid & 31;
    const int wm = w >> 1, wn = w & 1;
    const int bn = blockIdx.x, bm = blockIdx.y;
    const int KC = K >> 4;
    const int g = l >> 2, tq = l & 3;

    float acc[2][8][4];
    #pragma unroll
    for (int mi = 0; mi < 2; mi++)
        #pragma unroll
        for (int ni = 0; ni < 8; ni++)
            #pragma unroll
            for (int q = 0; q < 4; q++) acc[mi][ni][q] = 0.0f;

    const __half* Bsrc = Wimg + (size_t)bn*KC*2048;
    const int arow = tid >> 2, aseg = tid & 3;

    {
        #pragma unroll
        for (int r = 0; r < 2; r++) {
            int row = arow + r*64;
            cp16(smem_u32(&As[0][row][aseg*4]), A + (size_t)(bm*128 + row)*K + aseg*4);
        }
        cp16(smem_u32(&Bs[0][tid*8]), Bsrc + (size_t)tid*8);
        cp_commit();
    }

    int buf = 0;
    for (int kc = 0; kc < KC; kc++) {
        if (kc + 1 < KC) {
            #pragma unroll
            for (int r = 0; r < 2; r++) {
                int row = arow + r*64;
                cp16(smem_u32(&As[buf^1][row][aseg*4]),
                     A + (size_t)(bm*128 + row)*K + (kc+1)*16 + aseg*4);
            }
            cp16(smem_u32(&Bs[buf^1][tid*8]), Bsrc + (size_t)(kc+1)*2048 + tid*8);
            cp_commit();
            cp_wait1();
        } else {
            cp_wait0();
        }
        __syncthreads();

        uint32_t afr[2][4];
        #pragma unroll
        for (int mi = 0; mi < 2; mi++) {
            int r0 = wm*32 + mi*16 + g;
            float2 v0 = *(const float2*)&As[buf][r0    ][tq*2];
            float2 v1 = *(const float2*)&As[buf][r0 + 8][tq*2];
            float2 v2 = *(const float2*)&As[buf][r0    ][8 + tq*2];
            float2 v3 = *(const float2*)&As[buf][r0 + 8][8 + tq*2];
            afr[mi][0] = h2pack(v0.x, v0.y);
            afr[mi][1] = h2pack(v1.x, v1.y);
            afr[mi][2] = h2pack(v2.x, v2.y);
            afr[mi][3] = h2pack(v3.x, v3.y);
        }
        #pragma unroll
        for (int ni = 0; ni < 8; ni++) {
            uint2 bv = *(const uint2*)&Bs[buf][((wn*8 + ni)*32 + l)*4];
            uint32_t bfr[2] = { bv.x, bv.y };
            #pragma unroll
            for (int mi = 0; mi < 2; mi++)
                mma_fp16(acc[mi][ni], afr[mi], bfr);
        }
        __syncthreads();
        buf ^= 1;
    }

    #pragma unroll
    for (int mi = 0; mi < 2; mi++) {
        int row0 = bm*128 + wm*32 + mi*16 + g;
        #pragma unroll
        for (int ni = 0; ni < 8; ni++) {
            int col = bn*128 + wn*64 + ni*8 + tq*2;
            float b0 = bias[col], b1 = bias[col+1];
            if (mode == 0) {
                *(float2*)&C[(size_t)row0*N + col] =
                    make_float2(acc[mi][ni][0] + b0, acc[mi][ni][1] + b1);
                *(float2*)&C[(size_t)(row0 + 8)*N + col] =
                    make_float2(acc[mi][ni][2] + b0, acc[mi][ni][3] + b1);
            } else {
                int gate = col >> 10, cw = col & 1023;
                int s2 = cw >> 3, hl = cw & 7;
                int tt = row0 >> 6, bb = row0 & 63;
                size_t base = ((size_t)tt*NCTA + s2)*64;
                *(float2*)&C[(base + bb)*24 + gate*8 + hl] =
                    make_float2(acc[mi][ni][0] + b0, acc[mi][ni][1] + b1);
                *(float2*)&C[(base + bb + 8)*24 + gate*8 + hl] =
                    make_float2(acc[mi][ni][2] + b0, acc[mi][ni][3] + b1);
            }
        }
    }
}

// ---------------- persistent fp16-HMMA recurrence v10: 8-deep staging, flat barrier ----------------
extern __shared__ char smemRaw[];

__global__ __launch_bounds__(256, 1) void recur_mma()
{
    const int tid = threadIdx.x;
    const int w   = tid >> 5;
    const int l   = tid & 31;
    const int mw  = w & 1;           // M half: mt = 2*mw + mi
    const int ksp = w >> 1;          // K split 0..3
    const int s   = blockIdx.x;      // slice: h-cols s*8..s*8+7
    uint32_t smb  = smem_u32(smemRaw);
    uint32_t mbF0 = smb + SMO_MB;        // full[i] @ +8i, i=0..7
    uint32_t mbGX = smb + SMO_MB + 64;
    uint32_t mbBR = smb + SMO_MB + 72;
    const char* BresB = smemRaw + SMO_BRES;
    float* GH   = (float*)(smemRaw + SMO_GH);
    float* gxs  = (float*)(smemRaw + SMO_GXS);
    float* hist = (float*)(smemRaw + SMO_HIST);

    if (tid == 0) {
        #pragma unroll
        for (int i = 0; i < 8; i++) mbar_init(mbF0 + 8*i, 1);
        mbar_init(mbGX, 1); mbar_init(mbBR, 1);
    }
    __syncthreads();
    if (tid == 0) {
        mbar_expect_tx(mbBR, 49152);
        bulk_g2s(smb + SMO_BRES, (const char*)g_BImg16 + (size_t)s*49152, 49152, mbBR);
    }

    // hist ring init: hist[k][b][h8]
    for (int i = tid; i < K_*B_*8; i += 256) {
        int k = i >> 9, b = (i >> 3) & 63, h2 = i & 7;
        hist[i] = g_Hbuf[(size_t)k*BH + (size_t)b*H_ + s*8 + h2];
    }

    // epilogue constants
    const int hl8  = tid & 7;
    const int brow = tid >> 3;       // 0..31; b = brow, brow+32
    const int hc   = s*8 + hl8;
    float wk[K_];
    #pragma unroll
    for (int kk = 0; kk < K_; kk++) wk[kk] = g_w[kk*H_ + hc];
    // fp16 A-image write constants for k = hc
    const int a_ks16 = s >> 1;
    const int a_half = s & 1;
    const int a_tq   = hl8 >> 1;
    const int a_lo   = hl8 & 1;
    const int gg = l >> 2, tq = l & 3;

    mbar_wait(mbBR, 0);
    __syncthreads();

    for (int t = 0; t < T_; t++) {
        const char* aimg = (const char*)g_AImg16[t & 1];
        if (tid == 0) {
            mbar_expect_tx(mbGX, 6144);
            bulk_g2s(smb + SMO_GXS,
                     g_GX2 + (((size_t)t*NCTA + s)*64)*24, 6144, mbGX);
            // fire ALL 8 chunk copies immediately (1:1 buffers, parity = t&1)
            #pragma unroll
            for (int cp = 0; cp < 8; cp++) {
                mbar_expect_tx(mbF0 + 8*cp, 16384);
                bulk_g2s(smb + SMO_ABUF + cp*16384, aimg + (size_t)cp*16384, 16384, mbF0 + 8*cp);
            }
        }

        float acc[2][3][4];
        #pragma unroll
        for (int mi = 0; mi < 2; mi++)
            #pragma unroll
            for (int ni = 0; ni < 3; ni++)
                #pragma unroll
                for (int q = 0; q < 4; q++) acc[mi][ni][q] = 0.0f;

        #pragma unroll 1
        for (int c = 0; c < 8; c++) {
            mbar_wait(mbF0 + 8*c, (uint32_t)(t & 1));
            const char* Ab = smemRaw + SMO_ABUF + c*16384;
            #pragma unroll
            for (int kl = 0; kl < 2; kl++) {
                const int ksl = ksp*2 + kl;          // local ks16 in chunk (0..7)
                const int ksg = c*8 + ksl;           // global ks16 (0..63)
                uint32_t afr[2][4];
                *(uint4*)afr[0] = *(const uint4*)(Ab + ((size_t)((ksl*4 + 2*mw    )*32 + l))*16);
                *(uint4*)afr[1] = *(const uint4*)(Ab + ((size_t)((ksl*4 + 2*mw + 1)*32 + l))*16);
                #pragma unroll
                for (int ni = 0; ni < 3; ni++) {
                    uint2 bv = *(const uint2*)(BresB + ((size_t)((ksg*3 + ni)*32 + l))*8);
                    uint32_t bfr[2] = { bv.x, bv.y };
                    #pragma unroll
                    for (int mi = 0; mi < 2; mi++)
                        mma_fp16(acc[mi][ni], afr[mi], bfr);
                }
            }
        }
        __syncthreads();   // all buffer reads done -> GH alias safe

        // dump C fragments: GH[ksp][b][24]
        #pragma unroll
        for (int mi = 0; mi < 2; mi++) {
            int row0 = (2*mw + mi)*16 + gg;
            #pragma unroll
            for (int ni = 0; ni < 3; ni++) {
                int colb = ni*8 + tq*2;
                *(float2*)&GH[ksp*1536 + row0*24 + colb]       = make_float2(acc[mi][ni][0], acc[mi][ni][1]);
                *(float2*)&GH[ksp*1536 + (row0 + 8)*24 + colb] = make_float2(acc[mi][ni][2], acc[mi][ni][3]);
            }
        }
        __syncthreads();
        mbar_wait(mbGX, (uint32_t)(t & 1));

        // gates + fractional memory (2 (b,hl8) pairs per thread)
        __half* imgn = g_AImg16[(t + 1) & 1];
        #pragma unroll
        for (int i = 0; i < 2; i++) {
            int b = brow + i*32;
            int gi = b*24 + hl8*3;
            float gz = GH[gi] + GH[1536 + gi] + GH[3072 + gi] + GH[4608 + gi];
            float gr = GH[gi+1] + GH[1536 + gi+1] + GH[3072 + gi+1] + GH[4608 + gi+1];
            float gn = GH[gi+2] + GH[1536 + gi+2] + GH[3072 + gi+2] + GH[4608 + gi+2];
            float z = sigf(gxs[b*24 + hl8]          + gz);
            float r = sigf(gxs[b*24 + 8 + hl8]      + gr);
            float n = tanhf_fast(gxs[b*24 + 16 + hl8] + r*gn);
            float mem = 0.f;
            #pragma unroll
            for (int kk = 0; kk < K_; kk++)
                mem = fmaf(wk[kk], hist[((t + kk) & 7)*512 + b*8 + hl8], mem);
            float hn = (1.0f - z)*n + z*mem;
            hist[(t & 7)*512 + b*8 + hl8] = hn;
            g_Hbuf[(size_t)(K_ + t)*BH + (size_t)b*H_ + hc] = hn;
            // fp16 A-image write for next step
            int mt = b >> 4, r16 = b & 15;
            int g2 = r16 & 7, hi = r16 >> 3;
            int lane2 = g2*4 + a_tq;
            int rreg = hi + 2*a_half;
            imgn[(((a_ks16*4 + mt)*32 + lane2)*4 + rreg)*2 + a_lo] = __float2half(hn);
        }

        // flat grid barrier (proven fastest)
        __threadfence();
        __syncthreads();
        if (tid == 0) {
            atomicAdd(&g_bar, 1u);
            unsigned target = (unsigned)NCTA * (unsigned)(t + 1);
            while (*(volatile unsigned*)&g_bar < target) { __nanosleep(32); }
        }
        __syncthreads();
    }
}

// ---------------- tail ----------------
__global__ void tail_kernel(float* __restrict__ outTail)
{
    const int n = K_*BH;
    for (int i = blockIdx.x*blockDim.x + threadIdx.x; i < n; i += gridDim.x*blockDim.x)
        outTail[i] = g_Hbuf[(size_t)T_*BH + i];
}

// ---------------- launch ----------------
extern "C" void kernel_launch(void* const* d_in, const int* in_sizes, int n_in,
                              void* d_out, int out_size)
{
    const float* inputs = (const float*)d_in[0];
    const float* hidden = (const float*)d_in[1];
    const float* Wx     = (const float*)d_in[2];
    const float* Wh     = (const float*)d_in[3];
    const float* b      = (const float*)d_in[4];
    const float* Wo     = (const float*)d_in[5];
    const float* bo     = (const float*)d_in[6];
    const float* mp     = (const float*)d_in[7];
    float* out = (float*)d_out;

    void* gxp = nullptr; cudaGetSymbolAddress(&gxp, g_GX2);
    void* hbp = nullptr; cudaGetSymbolAddress(&hbp, g_Hbuf);
    void* wxi = nullptr; cudaGetSymbolAddress(&wxi, g_WxImg16);
    void* woi = nullptr; cudaGetSymbolAddress(&woi, g_WoImg);

    cudaFuncSetAttribute(recur_mma, cudaFuncAttributeMaxDynamicSharedMemorySize, SMEM_REQ);

    init_kernel<<<256, 256>>>(hidden, mp);
    prep_wht<<<512, 256>>>(Wh);
    prep_wimg16<<<512, 256>>>(Wx, (__half*)wxi, G3, I_);
    prep_wimg<<<512, 256>>>(Wo, (float*)woi, O_, H_);

    // GX2 = X @ Wx + b  (fp16 operands, fp32 accum, slice-major output)
    mma_gemm16<<<dim3(G3/128, (T_*B_)/128), 256>>>(inputs, (const __half*)wxi, b,
                                                   (float*)gxp, T_*B_, G3, I_, 1);
    // recurrence
    recur_mma<<<NCTA, 256, SMEM_REQ>>>();
    // outs = H_all @ Wo + bo  (tf32, clean output path)
    mma_gemm<<<dim3(O_/128, (T_*B_)/128), 256>>>((const float*)hbp + (size_t)K_*BH,
                                                 (const float*)woi, bo, out,
                                                 T_*B_, O_, H_, 0);
    if (out_size >= TBO + K_*BH)
        tail_kernel<<<256, 256>>>(out + TBO);
}

// round 16
// speedup vs baseline: 1.2405x; 1.0177x over previous
#include <cuda_runtime.h>
#include <cuda_fp16.h>
#include <cstdint>
#include <cstddef>

// ---------------- problem constants ----------------
#define T_   256
#define B_   64
#define I_   512
#define H_   1024
#define O_   512
#define K_   8
#define G3   3072
#define BH   65536
#define TBO  8388608

// ---------------- recurrence config (v10: 8-deep A staging, proven 1459us) ----------------
#define NCTA 128        // persistent CTAs; each owns 8 h-cols x 3 gates (N=24)
#define SMO_BRES 0          // resident Wh fp16 B-image: 49152
#define SMO_ABUF 49152      // 8 x 16384 A chunk buffers (1:1 with chunks) = 131072
#define SMO_GH   49152      // GH alias on A buffers (4x64x24 fp32 = 24576), post-loop only
#define SMO_GXS  180224     // gx slice stage: 6144
#define SMO_HIST 186368     // h history ring 8x64x8 fp32 = 16384
#define SMO_MB   202752     // full[8]@0..63, gx@64, bres@72
#define SMEM_REQ 202880

// ---------------- device scratch ----------------
__device__ float    g_GX2[(size_t)T_*NCTA*B_*24];  // gate preact, slice-major
__device__ float    g_Hbuf[(size_t)(K_+T_)*BH];    // hidden ring fp32
__device__ float    g_w[K_*H_];                    // GL weights, idx0 oldest
__device__ __half   g_AImg16[2][BH];               // h A-fragment fp16, ping-pong (128KB ea)
__device__ __half   g_BImg16[(size_t)NCTA*24576];  // Wh B-fragment-major fp16 (6MB)
__device__ __half   g_WxImg16[(size_t)I_*G3];      // Wx fragment-major fp16 (3MB)
__device__ __half   g_WoImg16[(size_t)H_*O_];      // Wo fragment-major fp16 (1MB)
__device__ unsigned g_bar;

// ---------------- helpers ----------------
__device__ __forceinline__ uint32_t smem_u32(const void* p) {
    uint32_t a; asm("{ .reg .u64 t; cvta.to.shared.u64 t, %1; cvt.u32.u64 %0, t; }" : "=r"(a) : "l"(p));
    return a;
}
__device__ __forceinline__ void mbar_init(uint32_t m, uint32_t c) {
    asm volatile("mbarrier.init.shared.b64 [%0], %1;" :: "r"(m), "r"(c) : "memory");
}
__device__ __forceinline__ void mbar_expect_tx(uint32_t m, uint32_t bytes) {
    asm volatile("mbarrier.arrive.expect_tx.shared.b64 _, [%0], %1;" :: "r"(m), "r"(bytes) : "memory");
}
__device__ __forceinline__ void mbar_wait(uint32_t m, uint32_t parity) {
    asm volatile(
        "{\n\t.reg .pred P;\n\t"
        "WL_%=:\n\t"
        "mbarrier.try_wait.parity.acquire.cta.shared::cta.b64 P, [%0], %1, 0x989680;\n\t"
        "@P bra WD_%=;\n\t"
        "bra WL_%=;\n\t"
        "WD_%=:\n\t}"
        :: "r"(m), "r"(parity) : "memory");
}
__device__ __forceinline__ void bulk_g2s(uint32_t dst, const void* src, uint32_t bytes, uint32_t mbar) {
    asm volatile("cp.async.bulk.shared::cluster.global.mbarrier::complete_tx::bytes [%0], [%1], %2, [%3];"
                 :: "r"(dst), "l"(src), "r"(bytes), "r"(mbar) : "memory");
}
__device__ __forceinline__ void cp16(uint32_t dst, const void* src) {
    asm volatile("cp.async.cg.shared.global [%0], [%1], 16;" :: "r"(dst), "l"(src));
}
__device__ __forceinline__ void cp_commit() { asm volatile("cp.async.commit_group;" ::: "memory"); }
__device__ __forceinline__ void cp_wait0() { asm volatile("cp.async.wait_group 0;" ::: "memory"); }
__device__ __forceinline__ void cp_wait1() { asm volatile("cp.async.wait_group 1;" ::: "memory"); }
__device__ __forceinline__ void mma_fp16(float* d, const uint32_t* a, const uint32_t* b) {
    asm("mma.sync.aligned.m16n8k16.row.col.f32.f16.f16.f32 "
        "{%0,%1,%2,%3},{%4,%5,%6,%7},{%8,%9},{%0,%1,%2,%3};"
        : "+f"(d[0]), "+f"(d[1]), "+f"(d[2]), "+f"(d[3])
        : "r"(a[0]), "r"(a[1]), "r"(a[2]), "r"(a[3]), "r"(b[0]), "r"(b[1]));
}
__device__ __forceinline__ uint32_t h2pack(float a, float b) {
    uint32_t r; asm("cvt.rn.f16x2.f32 %0, %1, %2;" : "=r"(r) : "f"(b), "f"(a));
    return r;
}
__device__ __forceinline__ float sigf(float x) { return 1.0f/(1.0f + __expf(-x)); }
__device__ __forceinline__ float tanhf_fast(float x) {
    float e = __expf(2.0f*x); return (e - 1.0f)/(e + 1.0f);
}

// fp16 A-fragment half-index for h[b][k]  (m16n8k16 .row A layout)
__device__ __forceinline__ int aimg16_idx(int b, int k) {
    int ks16 = k >> 4, k16 = k & 15;
    int mt = b >> 4, r16 = b & 15;
    int g = r16 & 7, hi = r16 >> 3;
    int half = k16 >> 3, tq = (k16 & 7) >> 1, lo = k16 & 1;
    int lane = g*4 + tq;
    int r = hi + 2*half;
    return (((ks16*4 + mt)*32 + lane)*4 + r)*2 + lo;
}

// ---------------- init ----------------
__global__ void init_kernel(const float* __restrict__ hid, const float* __restrict__ mp)
{
    int idx = blockIdx.x*blockDim.x + threadIdx.x;
    int stride = gridDim.x*blockDim.x;
    if (idx == 0) g_bar = 0u;
    if (idx < H_) {
        float a = 0.5f / (1.0f + expf(-mp[idx]));
        float c = 1.0f;
        #pragma unroll
        for (int i = 0; i < K_; i++) {
            c *= ((float)i + a) / ((float)i + 1.0f);
            g_w[(K_-1-i)*H_ + idx] = c;
        }
    }
    for (int i = idx; i < K_*BH; i += stride) g_Hbuf[i] = hid[i];
    const float* h0 = hid + (size_t)(K_-1)*BH;
    for (int i = idx; i < BH; i += stride) {
        int b = i >> 10, k = i & 1023;
        g_AImg16[0][aimg16_idx(b, k)] = __float2half(h0[(size_t)b*H_ + k]);
    }
}

// ---------------- prep: Wh -> fp16 B-fragment image (slice = 8 h-cols, m16n8k16 .col B) ----------------
__global__ void prep_wht(const float* __restrict__ Wh)
{
    int idx = blockIdx.x*blockDim.x + threadIdx.x;
    int stride = gridDim.x*blockDim.x;
    const int total = H_*G3;
    for (int i = idx; i < total; i += stride) {
        int k = i / G3, col = i - k*G3;
        int gate = col >> 10, cw = col & 1023;
        int s = cw >> 3, hl8 = cw & 7;
        int nl = hl8*3 + gate;
        int nt = nl >> 3, g = nl & 7;
        int ks16 = k >> 4, k16 = k & 15;
        int r = k16 >> 3, tq = (k16 & 7) >> 1, lo = k16 & 1;
        int lane = g*4 + tq;
        size_t dst = ((((size_t)s*64 + ks16)*3 + nt)*32 + lane)*4 + r*2 + lo;
        g_BImg16[dst] = __float2half(Wh[i]);
    }
}

// ---------------- prep: weight -> fp16 GEMM B-fragment image (m16n8k16 .col B) ----------------
__global__ void prep_wimg16(const float* __restrict__ W, __half* __restrict__ img, int N, int K)
{
    int idx = blockIdx.x*blockDim.x + threadIdx.x;
    int stride = gridDim.x*blockDim.x;
    const int total = K*N, KC = K >> 4;
    for (int i = idx; i < total; i += stride) {
        int k = i / N, n = i - k*N;
        int nb = n >> 7, ntl = (n >> 3) & 15, g = n & 7;
        int ks16 = k >> 4, k16 = k & 15;
        int r = k16 >> 3, tq = (k16 & 7) >> 1, lo = k16 & 1;
        int lane = g*4 + tq;
        size_t dst = ((((size_t)nb*KC + ks16)*16 + ntl)*32 + lane)*4 + r*2 + lo;
        img[dst] = __float2half(W[i]);
    }
}

// ---------------- fp16 HMMA GEMM: C = A @ W + bias (gx AND out paths) ----------------
__global__ __launch_bounds__(256) void mma_gemm16(
    const float* __restrict__ A, const __half* __restrict__ Wimg,
    const float* __restrict__ bias, float* __restrict__ C,
    int M, int N, int K, int mode)
{
    __shared__ float As[2][128][20];
    __shared__ __half Bs[2][2048];
    const int tid = threadIdx.x;
    const int w = tid >> 5, l = tid & 31;
    const int wm = w >> 1, wn = w & 1;
    const int bn = blockIdx.x, bm = blockIdx.y;
    const int KC = K >> 4;
    const int g = l >> 2, tq = l & 3;

    float acc[2][8][4];
    #pragma unroll
    for (int mi = 0; mi < 2; mi++)
        #pragma unroll
        for (int ni = 0; ni < 8; ni++)
            #pragma unroll
            for (int q = 0; q < 4; q++) acc[mi][ni][q] = 0.0f;

    const __half* Bsrc = Wimg + (size_t)bn*KC*2048;
    const int arow = tid >> 2, aseg = tid & 3;

    {
        #pragma unroll
        for (int r = 0; r < 2; r++) {
            int row = arow + r*64;
            cp16(smem_u32(&As[0][row][aseg*4]), A + (size_t)(bm*128 + row)*K + aseg*4);
        }
        cp16(smem_u32(&Bs[0][tid*8]), Bsrc + (size_t)tid*8);
        cp_commit();
    }

    int buf = 0;
    for (int kc = 0; kc < KC; kc++) {
        if (kc + 1 < KC) {
            #pragma unroll
            for (int r = 0; r < 2; r++) {
                int row = arow + r*64;
                cp16(smem_u32(&As[buf^1][row][aseg*4]),
                     A + (size_t)(bm*128 + row)*K + (kc+1)*16 + aseg*4);
            }
            cp16(smem_u32(&Bs[buf^1][tid*8]), Bsrc + (size_t)(kc+1)*2048 + tid*8);
            cp_commit();
            cp_wait1();
        } else {
            cp_wait0();
        }
        __syncthreads();

        uint32_t afr[2][4];
        #pragma unroll
        for (int mi = 0; mi < 2; mi++) {
            int r0 = wm*32 + mi*16 + g;
            float2 v0 = *(const float2*)&As[buf][r0    ][tq*2];
            float2 v1 = *(const float2*)&As[buf][r0 + 8][tq*2];
            float2 v2 = *(const float2*)&As[buf][r0    ][8 + tq*2];
            float2 v3 = *(const float2*)&As[buf][r0 + 8][8 + tq*2];
            afr[mi][0] = h2pack(v0.x, v0.y);
            afr[mi][1] = h2pack(v1.x, v1.y);
            afr[mi][2] = h2pack(v2.x, v2.y);
            afr[mi][3] = h2pack(v3.x, v3.y);
        }
        #pragma unroll
        for (int ni = 0; ni < 8; ni++) {
            uint2 bv = *(const uint2*)&Bs[buf][((wn*8 + ni)*32 + l)*4];
            uint32_t bfr[2] = { bv.x, bv.y };
            #pragma unroll
            for (int mi = 0; mi < 2; mi++)
                mma_fp16(acc[mi][ni], afr[mi], bfr);
        }
        __syncthreads();
        buf ^= 1;
    }

    #pragma unroll
    for (int mi = 0; mi < 2; mi++) {
        int row0 = bm*128 + wm*32 + mi*16 + g;
        #pragma unroll
        for (int ni = 0; ni < 8; ni++) {
            int col = bn*128 + wn*64 + ni*8 + tq*2;
            float b0 = bias[col], b1 = bias[col+1];
            if (mode == 0) {
                *(float2*)&C[(size_t)row0*N + col] =
                    make_float2(acc[mi][ni][0] + b0, acc[mi][ni][1] + b1);
                *(float2*)&C[(size_t)(row0 + 8)*N + col] =
                    make_float2(acc[mi][ni][2] + b0, acc[mi][ni][3] + b1);
            } else {
                int gate = col >> 10, cw = col & 1023;
                int s2 = cw >> 3, hl = cw & 7;
                int tt = row0 >> 6, bb = row0 & 63;
                size_t base = ((size_t)tt*NCTA + s2)*64;
                *(float2*)&C[(base + bb)*24 + gate*8 + hl] =
                    make_float2(acc[mi][ni][0] + b0, acc[mi][ni][1] + b1);
                *(float2*)&C[(base + bb + 8)*24 + gate*8 + hl] =
                    make_float2(acc[mi][ni][2] + b0, acc[mi][ni][3] + b1);
            }
        }
    }
}

// ---------------- persistent fp16-HMMA recurrence v10 (EXACT R15, proven) ----------------
extern __shared__ char smemRaw[];

__global__ __launch_bounds__(256, 1) void recur_mma()
{
    const int tid = threadIdx.x;
    const int w   = tid >> 5;
    const int l   = tid & 31;
    const int mw  = w & 1;           // M half: mt = 2*mw + mi
    const int ksp = w >> 1;          // K split 0..3
    const int s   = blockIdx.x;      // slice: h-cols s*8..s*8+7
    uint32_t smb  = smem_u32(smemRaw);
    uint32_t mbF0 = smb + SMO_MB;        // full[i] @ +8i, i=0..7
    uint32_t mbGX = smb + SMO_MB + 64;
    uint32_t mbBR = smb + SMO_MB + 72;
    const char* BresB = smemRaw + SMO_BRES;
    float* GH   = (float*)(smemRaw + SMO_GH);
    float* gxs  = (float*)(smemRaw + SMO_GXS);
    float* hist = (float*)(smemRaw + SMO_HIST);

    if (tid == 0) {
        #pragma unroll
        for (int i = 0; i < 8; i++) mbar_init(mbF0 + 8*i, 1);
        mbar_init(mbGX, 1); mbar_init(mbBR, 1);
    }
    __syncthreads();
    if (tid == 0) {
        mbar_expect_tx(mbBR, 49152);
        bulk_g2s(smb + SMO_BRES, (const char*)g_BImg16 + (size_t)s*49152, 49152, mbBR);
    }

    // hist ring init: hist[k][b][h8]
    for (int i = tid; i < K_*B_*8; i += 256) {
        int k = i >> 9, b = (i >> 3) & 63, h2 = i & 7;
        hist[i] = g_Hbuf[(size_t)k*BH + (size_t)b*H_ + s*8 + h2];
    }

    // epilogue constants
    const int hl8  = tid & 7;
    const int brow = tid >> 3;       // 0..31; b = brow, brow+32
    const int hc   = s*8 + hl8;
    float wk[K_];
    #pragma unroll
    for (int kk = 0; kk < K_; kk++) wk[kk] = g_w[kk*H_ + hc];
    // fp16 A-image write constants for k = hc
    const int a_ks16 = s >> 1;
    const int a_half = s & 1;
    const int a_tq   = hl8 >> 1;
    const int a_lo   = hl8 & 1;
    const int gg = l >> 2, tq = l & 3;

    mbar_wait(mbBR, 0);
    __syncthreads();

    for (int t = 0; t < T_; t++) {
        const char* aimg = (const char*)g_AImg16[t & 1];
        if (tid == 0) {
            mbar_expect_tx(mbGX, 6144);
            bulk_g2s(smb + SMO_GXS,
                     g_GX2 + (((size_t)t*NCTA + s)*64)*24, 6144, mbGX);
            // fire ALL 8 chunk copies immediately (1:1 buffers, parity = t&1)
            #pragma unroll
            for (int cp = 0; cp < 8; cp++) {
                mbar_expect_tx(mbF0 + 8*cp, 16384);
                bulk_g2s(smb + SMO_ABUF + cp*16384, aimg + (size_t)cp*16384, 16384, mbF0 + 8*cp);
            }
        }

        float acc[2][3][4];
        #pragma unroll
        for (int mi = 0; mi < 2; mi++)
            #pragma unroll
            for (int ni = 0; ni < 3; ni++)
                #pragma unroll
                for (int q = 0; q < 4; q++) acc[mi][ni][q] = 0.0f;

        #pragma unroll 1
        for (int c = 0; c < 8; c++) {
            mbar_wait(mbF0 + 8*c, (uint32_t)(t & 1));
            const char* Ab = smemRaw + SMO_ABUF + c*16384;
            #pragma unroll
            for (int kl = 0; kl < 2; kl++) {
                const int ksl = ksp*2 + kl;          // local ks16 in chunk (0..7)
                const int ksg = c*8 + ksl;           // global ks16 (0..63)
                uint32_t afr[2][4];
                *(uint4*)afr[0] = *(const uint4*)(Ab + ((size_t)((ksl*4 + 2*mw    )*32 + l))*16);
                *(uint4*)afr[1] = *(const uint4*)(Ab + ((size_t)((ksl*4 + 2*mw + 1)*32 + l))*16);
                #pragma unroll
                for (int ni = 0; ni < 3; ni++) {
                    uint2 bv = *(const uint2*)(BresB + ((size_t)((ksg*3 + ni)*32 + l))*8);
                    uint32_t bfr[2] = { bv.x, bv.y };
                    #pragma unroll
                    for (int mi = 0; mi < 2; mi++)
                        mma_fp16(acc[mi][ni], afr[mi], bfr);
                }
            }
        }
        __syncthreads();   // all buffer reads done -> GH alias safe

        // dump C fragments: GH[ksp][b][24]
        #pragma unroll
        for (int mi = 0; mi < 2; mi++) {
            int row0 = (2*mw + mi)*16 + gg;
            #pragma unroll
            for (int ni = 0; ni < 3; ni++) {
                int colb = ni*8 + tq*2;
                *(float2*)&GH[ksp*1536 + row0*24 + colb]       = make_float2(acc[mi][ni][0], acc[mi][ni][1]);
                *(float2*)&GH[ksp*1536 + (row0 + 8)*24 + colb] = make_float2(acc[mi][ni][2], acc[mi][ni][3]);
            }
        }
        __syncthreads();
        mbar_wait(mbGX, (uint32_t)(t & 1));

        // gates + fractional memory (2 (b,hl8) pairs per thread)
        __half* imgn = g_AImg16[(t + 1) & 1];
        #pragma unroll
        for (int i = 0; i < 2; i++) {
            int b = brow + i*32;
            int gi = b*24 + hl8*3;
            float gz = GH[gi] + GH[1536 + gi] + GH[3072 + gi] + GH[4608 + gi];
            float gr = GH[gi+1] + GH[1536 + gi+1] + GH[3072 + gi+1] + GH[4608 + gi+1];
            float gn = GH[gi+2] + GH[1536 + gi+2] + GH[3072 + gi+2] + GH[4608 + gi+2];
            float z = sigf(gxs[b*24 + hl8]          + gz);
            float r = sigf(gxs[b*24 + 8 + hl8]      + gr);
            float n = tanhf_fast(gxs[b*24 + 16 + hl8] + r*gn);
            float mem = 0.f;
            #pragma unroll
            for (int kk = 0; kk < K_; kk++)
                mem = fmaf(wk[kk], hist[((t + kk) & 7)*512 + b*8 + hl8], mem);
            float hn = (1.0f - z)*n + z*mem;
            hist[(t & 7)*512 + b*8 + hl8] = hn;
            g_Hbuf[(size_t)(K_ + t)*BH + (size_t)b*H_ + hc] = hn;
            // fp16 A-image write for next step
            int mt = b >> 4, r16 = b & 15;
            int g2 = r16 & 7, hi = r16 >> 3;
            int lane2 = g2*4 + a_tq;
            int rreg = hi + 2*a_half;
            imgn[(((a_ks16*4 + mt)*32 + lane2)*4 + rreg)*2 + a_lo] = __float2half(hn);
        }

        // flat grid barrier (proven fastest)
        __threadfence();
        __syncthreads();
        if (tid == 0) {
            atomicAdd(&g_bar, 1u);
            unsigned target = (unsigned)NCTA * (unsigned)(t + 1);
            while (*(volatile unsigned*)&g_bar < target) { __nanosleep(32); }
        }
        __syncthreads();
    }
}

// ---------------- tail ----------------
__global__ void tail_kernel(float* __restrict__ outTail)
{
    const int n = K_*BH;
    for (int i = blockIdx.x*blockDim.x + threadIdx.x; i < n; i += gridDim.x*blockDim.x)
        outTail[i] = g_Hbuf[(size_t)T_*BH + i];
}

// ---------------- launch ----------------
extern "C" void kernel_launch(void* const* d_in, const int* in_sizes, int n_in,
                              void* d_out, int out_size)
{
    const float* inputs = (const float*)d_in[0];
    const float* hidden = (const float*)d_in[1];
    const float* Wx     = (const float*)d_in[2];
    const float* Wh     = (const float*)d_in[3];
    const float* b      = (const float*)d_in[4];
    const float* Wo     = (const float*)d_in[5];
    const float* bo     = (const float*)d_in[6];
    const float* mp     = (const float*)d_in[7];
    float* out = (float*)d_out;

    void* gxp = nullptr; cudaGetSymbolAddress(&gxp, g_GX2);
    void* hbp = nullptr; cudaGetSymbolAddress(&hbp, g_Hbuf);
    void* wxi = nullptr; cudaGetSymbolAddress(&wxi, g_WxImg16);
    void* woi = nullptr; cudaGetSymbolAddress(&woi, g_WoImg16);

    cudaFuncSetAttribute(recur_mma, cudaFuncAttributeMaxDynamicSharedMemorySize, SMEM_REQ);

    init_kernel<<<256, 256>>>(hidden, mp);
    prep_wht<<<512, 256>>>(Wh);
    prep_wimg16<<<512, 256>>>(Wx, (__half*)wxi, G3, I_);
    prep_wimg16<<<256, 256>>>(Wo, (__half*)woi, O_, H_);

    // GX2 = X @ Wx + b  (fp16 operands, fp32 accum, slice-major output)
    mma_gemm16<<<dim3(G3/128, (T_*B_)/128), 256>>>(inputs, (const __half*)wxi, b,
                                                   (float*)gxp, T_*B_, G3, I_, 1);
    // recurrence (exact R15)
    recur_mma<<<NCTA, 256, SMEM_REQ>>>();
    // outs = H_all @ Wo + bo  (fp16 operands, fp32 accum)
    mma_gemm16<<<dim3(O_/128, (T_*B_)/128), 256>>>((const float*)hbp + (size_t)K_*BH,
                                                   (const __half*)woi, bo, out,
                                                   T_*B_, O_, H_, 0);
    if (out_size >= TBO + K_*BH)
        tail_kernel<<<256, 256>>>(out + TBO);
}